// round 10
// baseline (speedup 1.0000x reference)
#include <cuda_runtime.h>
#include <cstdint>

#define SLEN 2048
#define BATCH 64
#define HID 512
#define G4 2048
#define NBG 4            // batch groups (independent recurrences)
#define NUG 32           // unit groups
#define NBLK (NBG*NUG)   // 128 blocks
#define UPB 16           // units per block
#define BPB 16           // batches per block
#define TPB 512

// ---------------- scratch (device globals) ----------------
static __device__ float g_xp[(size_t)SLEN * G4 * BATCH];      // [s][g][b], 1 GiB
static __device__ float g_h[2][NBG][HID][BPB];                // ping-pong h, [bg][k][b_local]
static __device__ __align__(16) int g_flag[NBG][NUG];         // steps published per block

// ---------------- packed f32x2 helpers ----------------
__device__ __forceinline__ uint64_t f2_pack(float x, float y) {
    uint64_t r; uint32_t xu = __float_as_uint(x), yu = __float_as_uint(y);
    asm("mov.b64 %0, {%1, %2};" : "=l"(r) : "r"(xu), "r"(yu));
    return r;
}
__device__ __forceinline__ uint64_t f2_dup(float x) {
    uint64_t r; uint32_t xu = __float_as_uint(x);
    asm("mov.b64 %0, {%1, %1};" : "=l"(r) : "r"(xu));
    return r;
}
__device__ __forceinline__ void f2_fma(uint64_t& d, uint64_t a, uint64_t b) {
    asm("fma.rn.f32x2 %0, %1, %2, %0;" : "+l"(d) : "l"(a), "l"(b));
}
__device__ __forceinline__ void f2_add(uint64_t& d, uint64_t a) {
    asm("add.rn.f32x2 %0, %1, %0;" : "+l"(d) : "l"(a));
}
__device__ __forceinline__ float2 f2_unpack(uint64_t v) {
    uint32_t lo, hi;
    asm("mov.b64 {%0, %1}, %2;" : "=r"(lo), "=r"(hi) : "l"(v));
    return make_float2(__uint_as_float(lo), __uint_as_float(hi));
}

// ---------------- kernel 0: reset flags + transpose h_prev into g_h[1] ----------------
__global__ void init_kernel(const float* __restrict__ h_prev) {
    int idx = blockIdx.x * blockDim.x + threadIdx.x;   // 32768 threads
    if (idx < NBLK) ((int*)g_flag)[idx] = 0;
    int bg = idx >> 13;            // /8192
    int k  = (idx >> 4) & 511;
    int b  = idx & 15;
    g_h[1][bg][k][b] = h_prev[(size_t)(bg * BPB + b) * HID + k];
}

// ---------------- kernel 1: x_proj GEMM (FMA-bound f32x2) ----------------
__global__ __launch_bounds__(256, 2) void xproj_gemm_kernel(
    const float* __restrict__ A,    // (131072, 512)
    const float* __restrict__ W,    // (2048, 512)
    const float* __restrict__ bi,
    const float* __restrict__ bh)
{
    __shared__ float Ash[16][132];
    __shared__ float Bsh[16][132];

    const int tid = threadIdx.x;
    const int tx = tid & 15;
    const int ty = tid >> 4;
    const int m0 = blockIdx.x * 128;
    const int g0 = blockIdx.y * 128;

    uint64_t acc[8][4];
#pragma unroll
    for (int g = 0; g < 8; ++g)
#pragma unroll
        for (int p = 0; p < 4; ++p) acc[g][p] = 0ull;

    for (int kt = 0; kt < 32; ++kt) {
        const int k0 = kt * 16;
#pragma unroll
        for (int i = 0; i < 2; ++i) {
            int idx = tid + i * 256;
            int r = idx >> 2, c4 = idx & 3;
            float4 va = *(const float4*)(A + (size_t)(m0 + r) * 512 + k0 + c4 * 4);
            Ash[c4 * 4 + 0][r] = va.x; Ash[c4 * 4 + 1][r] = va.y;
            Ash[c4 * 4 + 2][r] = va.z; Ash[c4 * 4 + 3][r] = va.w;
            float4 vb = *(const float4*)(W + (size_t)(g0 + r) * 512 + k0 + c4 * 4);
            Bsh[c4 * 4 + 0][r] = vb.x; Bsh[c4 * 4 + 1][r] = vb.y;
            Bsh[c4 * 4 + 2][r] = vb.z; Bsh[c4 * 4 + 3][r] = vb.w;
        }
        __syncthreads();
#pragma unroll
        for (int kk = 0; kk < 16; ++kk) {
            uint64_t a[4];
            const uint64_t* ap = (const uint64_t*)&Ash[kk][ty * 8];
            a[0] = ap[0]; a[1] = ap[1]; a[2] = ap[2]; a[3] = ap[3];
            float4 q0 = *(const float4*)&Bsh[kk][tx * 8];
            float4 q1 = *(const float4*)&Bsh[kk][tx * 8 + 4];
            float bv[8] = {q0.x, q0.y, q0.z, q0.w, q1.x, q1.y, q1.z, q1.w};
#pragma unroll
            for (int g = 0; g < 8; ++g) {
                uint64_t bd = f2_dup(bv[g]);
                f2_fma(acc[g][0], a[0], bd);
                f2_fma(acc[g][1], a[1], bd);
                f2_fma(acc[g][2], a[2], bd);
                f2_fma(acc[g][3], a[3], bd);
            }
        }
        __syncthreads();
    }

    const int s  = blockIdx.x * 2 + (ty >> 3);
    const int b0 = (ty & 7) * 8;
#pragma unroll
    for (int g = 0; g < 8; ++g) {
        int gg = g0 + tx * 8 + g;
        float bsum = __ldg(bi + gg) + __ldg(bh + gg);
        float2 p0 = f2_unpack(acc[g][0]);
        float2 p1 = f2_unpack(acc[g][1]);
        float2 p2 = f2_unpack(acc[g][2]);
        float2 p3 = f2_unpack(acc[g][3]);
        float4 v0 = make_float4(p0.x + bsum, p0.y + bsum, p1.x + bsum, p1.y + bsum);
        float4 v1 = make_float4(p2.x + bsum, p2.y + bsum, p3.x + bsum, p3.y + bsum);
        float* dst = g_xp + ((size_t)s * G4 + gg) * 64 + b0;
        *(float4*)dst = v0;
        *(float4*)(dst + 4) = v1;
    }
}

// ---------------- kernel 2: persistent recurrent LSTM ----------------
// 128 blocks = (bg in 4) x (ug in 32); block owns 16 units x 16 batches.
// SYNC REWRITE vs R8 (which measured 9.5us/step):
//  - publish: ONE st.release.gpu of this block's flag (no atomic convoy, no membar.gl)
//  - wait: warp 0 polls all 32 bg flags in parallel (1 lane = 1 flag, coalesced 128B)
//    via __ballot_sync loop -> one L2 round trip instead of atomic serialization
//  - out[] stores moved AFTER the publish (SMEM transpose -> 16B coalesced stores)
__global__ __launch_bounds__(TPB, 1) void lstm_rec_kernel(
    const float* __restrict__ c_prev,
    const float* __restrict__ Whh,
    float* __restrict__ out)
{
    extern __shared__ char smp[];
    uint64_t* W2u    = (uint64_t*)smp;           // [512][32] gate-row pairs, 128 KB
    char*     region = smp + 131072;             // 64 KB: hst (per-warp 2KB) / partials
    float*    zb     = (float*)(smp + 196608);   // [64 rows][16 b], 4 KB
    float*    hbuf   = (float*)(smp + 200704);   // [16 bb][16 u], 1 KB

    const int tid  = threadIdx.x;
    const int w    = tid >> 5;
    const int lane = tid & 31;
    const int bg   = blockIdx.x & 3;
    const int ug   = blockIdx.x >> 2;
    const int rh   = lane >> 2;    // row-pair group 0..7
    const int bh   = lane & 3;     // b-quad 0..3
    const int u    = tid >> 4;     // activation: unit 0..15 (tid<256)
    const int bb   = tid & 15;     // activation: batch local

    // --- W setup: W2u[k*32+rp] = (W[row 2rp][k], W[row 2rp+1][k]) ---
    for (int idx = tid; idx < 512 * 32; idx += TPB) {
        int k = idx >> 5, rp = idx & 31;
        int r0 = rp * 2, r1 = rp * 2 + 1;
        int gr0 = (r0 >> 4) * HID + ug * UPB + (r0 & 15);
        int gr1 = (r1 >> 4) * HID + ug * UPB + (r1 & 15);
        W2u[idx] = f2_pack(Whh[(size_t)gr0 * HID + k], Whh[(size_t)gr1 * HID + k]);
    }

    float c = 0.f, xi = 0.f, xf = 0.f, xg = 0.f, xo = 0.f;
    if (tid < 256) {
        c  = c_prev[(size_t)(bg * BPB + bb) * HID + ug * UPB + u];
        size_t xb = (size_t)(ug * UPB + u) * 64 + bg * BPB + bb;
        xi = g_xp[xb + (size_t)(0 * HID) * 64];
        xf = g_xp[xb + (size_t)(1 * HID) * 64];
        xg = g_xp[xb + (size_t)(2 * HID) * 64];
        xo = g_xp[xb + (size_t)(3 * HID) * 64];
    }

    float* hst = (float*)(region + w * 2048);              // [32 k local][16 b]
    uint32_t hst_s = (uint32_t)__cvta_generic_to_shared(hst);
    const uint64_t* W2w = W2u + (size_t)w * 32 * 32;       // warp's global-k slice

    __syncthreads();   // W2u ready

    for (int s = 0; s < SLEN; ++s) {
        // --- wait: warp 0 polls all 32 flags of this bg in parallel ---
        if (w == 0) {
            const int* fpp = &g_flag[bg][lane];
            int v;
            do {
                asm volatile("ld.acquire.gpu.global.u32 %0, [%1];"
                             : "=r"(v) : "l"(fpp) : "memory");
            } while (__ballot_sync(0xffffffffu, v < s) != 0u);
        }
        __syncthreads();

        // --- stage this warp's 2KB h slice (2 pipelined chunks) ---
        const float* hsrc = &g_h[(s + 1) & 1][bg][w * 32][0];
#pragma unroll
        for (int ch = 0; ch < 2; ++ch) {
#pragma unroll
            for (int i = 0; i < 2; ++i) {
                int flat = ch * 64 + i * 32 + lane;        // 16B unit index
                asm volatile("cp.async.cg.shared.global [%0], [%1], 16;"
                             :: "r"(hst_s + flat * 16), "l"(hsrc + flat * 4));
            }
            asm volatile("cp.async.commit_group;");
        }

        uint64_t acc[16];
#pragma unroll
        for (int i = 0; i < 16; ++i) acc[i] = 0ull;

        const float zxi = xi, zxf = xf, zxg = xg, zxo = xo;
        if (tid < 256 && s + 1 < SLEN) {     // prefetch next xp (hidden by compute)
            size_t xb = ((size_t)(s + 1) * G4) * 64 + (size_t)(ug * UPB + u) * 64 + bg * BPB + bb;
            xi = g_xp[xb + (size_t)(0 * HID) * 64];
            xf = g_xp[xb + (size_t)(1 * HID) * 64];
            xg = g_xp[xb + (size_t)(2 * HID) * 64];
            xo = g_xp[xb + (size_t)(3 * HID) * 64];
        }

#pragma unroll
        for (int ch = 0; ch < 2; ++ch) {
            if (ch == 0) asm volatile("cp.async.wait_group 1;");
            else         asm volatile("cp.async.wait_group 0;");
            __syncwarp();
#pragma unroll
            for (int kk = 0; kk < 16; ++kk) {
                const int k = ch * 16 + kk;                // local k
                float4 hq = *(const float4*)(hst + k * 16 + bh * 4);
                uint64_t h0 = f2_dup(hq.x), h1 = f2_dup(hq.y);
                uint64_t h2 = f2_dup(hq.z), h3 = f2_dup(hq.w);
                const uint64_t* Wk = W2w + (size_t)k * 32;
                ulonglong2 wA = *(const ulonglong2*)(Wk + rh * 4);
                ulonglong2 wB = *(const ulonglong2*)(Wk + rh * 4 + 2);
                f2_fma(acc[0],  h0, wA.x); f2_fma(acc[1],  h1, wA.x);
                f2_fma(acc[2],  h2, wA.x); f2_fma(acc[3],  h3, wA.x);
                f2_fma(acc[4],  h0, wA.y); f2_fma(acc[5],  h1, wA.y);
                f2_fma(acc[6],  h2, wA.y); f2_fma(acc[7],  h3, wA.y);
                f2_fma(acc[8],  h0, wB.x); f2_fma(acc[9],  h1, wB.x);
                f2_fma(acc[10], h2, wB.x); f2_fma(acc[11], h3, wB.x);
                f2_fma(acc[12], h0, wB.y); f2_fma(acc[13], h1, wB.y);
                f2_fma(acc[14], h2, wB.y); f2_fma(acc[15], h3, wB.y);
            }
        }

        // --- partials into aliased region ---
        __syncthreads();
        {
            uint64_t* part = (uint64_t*)region + (size_t)w * 512;
#pragma unroll
            for (int pi = 0; pi < 4; ++pi) {
#pragma unroll
                for (int bi = 0; bi < 4; bi += 2) {
                    int p = (rh * 4 + pi) * 16 + bh * 4 + bi;
                    *(ulonglong2*)(part + p) =
                        make_ulonglong2(acc[pi * 4 + bi], acc[pi * 4 + bi + 1]);
                }
            }
        }
        __syncthreads();

        // --- reduce 16 warps: thread t owns pair index t ---
        {
            const uint64_t* part = (const uint64_t*)region;
            uint64_t e = part[tid];
            uint64_t o = part[512 + tid];
#pragma unroll
            for (int ww = 2; ww < 16; ww += 2) {
                f2_add(e, part[ww * 512 + tid]);
                f2_add(o, part[(ww + 1) * 512 + tid]);
            }
            f2_add(e, o);
            float2 zp = f2_unpack(e);
            int base = (tid >> 4) * 32 + (tid & 15);   // row 2rp, batch b
            zb[base] = zp.x;
            zb[base + 16] = zp.y;                      // row 2rp+1
        }
        __syncthreads();

        // --- activations: thread (u, bb), tid<256 ---
        if (tid < 256) {
            float z_i = zb[(0 * 16 + u) * 16 + bb] + zxi;
            float z_f = zb[(1 * 16 + u) * 16 + bb] + zxf;
            float z_g = zb[(2 * 16 + u) * 16 + bb] + zxg;
            float z_o = zb[(3 * 16 + u) * 16 + bb] + zxo;
            float ig = 1.f / (1.f + __expf(-z_i));
            float fg = 1.f / (1.f + __expf(-z_f));
            float gt = tanhf(z_g);
            float og = 1.f / (1.f + __expf(-z_o));
            c = fg * c + ig * gt;
            float h = og * tanhf(c);

            g_h[s & 1][bg][ug * UPB + u][bb] = h;      // coalesced (bb consecutive)
            hbuf[bb * 16 + u] = h;                     // for post-publish out store

            if (s == SLEN - 1) {
                const size_t SBH = (size_t)SLEN * BATCH * HID;
                size_t o2 = (size_t)(bg * BPB + bb) * HID + ug * UPB + u;
                out[SBH + o2] = h;                          // h_f
                out[SBH + (size_t)BATCH * HID + o2] = c;    // c_f
            }
        }
        __syncthreads();

        // --- publish: ONE release store (orders prior g_h stores, no membar) ---
        if (tid == 0) {
            asm volatile("st.release.gpu.global.u32 [%0], %1;"
                         :: "l"(&g_flag[bg][ug]), "r"((unsigned)(s + 1)) : "memory");
        }

        // --- out stores OFF the publish path: 16 rows x 4 float4 ---
        if (tid < 64) {
            int row = tid >> 2, q = tid & 3;
            float4 hv = *(const float4*)(hbuf + row * 16 + q * 4);
            *(float4*)(out + ((size_t)s * BATCH + bg * BPB + row) * HID
                             + ug * UPB + q * 4) = hv;
        }
    }
}

// ---------------- launch ----------------
extern "C" void kernel_launch(void* const* d_in, const int* in_sizes, int n_in,
                              void* d_out, int out_size) {
    (void)in_sizes; (void)n_in; (void)out_size;
    const float* input  = (const float*)d_in[0];  // (2048, 64, 512)
    const float* h_prev = (const float*)d_in[1];  // (64, 512)
    const float* c_prev = (const float*)d_in[2];  // (64, 512)
    const float* w_ih   = (const float*)d_in[3];  // (2048, 512)
    const float* w_hh   = (const float*)d_in[4];  // (2048, 512)
    const float* b_ih   = (const float*)d_in[5];  // (2048,)
    const float* b_hh   = (const float*)d_in[6];  // (2048,)
    float* out = (float*)d_out;

    cudaFuncSetAttribute(lstm_rec_kernel,
                         cudaFuncAttributeMaxDynamicSharedMemorySize, 201728);

    init_kernel<<<128, 256>>>(h_prev);

    dim3 g1(131072 / 128, 2048 / 128);   // (1024, 16)
    xproj_gemm_kernel<<<g1, 256>>>(input, w_ih, b_ih, b_hh);

    lstm_rec_kernel<<<NBLK, TPB, 201728>>>(c_prev, w_hh, out);
}

// round 11
// speedup vs baseline: 1.2918x; 1.2918x over previous
#include <cuda_runtime.h>
#include <cstdint>

#define SLEN 2048
#define BATCH 64
#define HID 512
#define G4 2048
#define NBLK 128
#define TPB 256

// ---------------- scratch (device globals) ----------------
static __device__ float g_xp[(size_t)SLEN * G4 * BATCH];   // [s][g][b], 1 GiB
static __device__ float g_hT[2][HID * BATCH];              // transposed h [j][b], ping-pong
static __device__ unsigned g_leaf[8];
static __device__ unsigned g_root;
static __device__ unsigned g_epoch;

// ---------------- packed f32x2 helpers ----------------
__device__ __forceinline__ uint64_t f2_pack(float x, float y) {
    uint64_t r; uint32_t xu = __float_as_uint(x), yu = __float_as_uint(y);
    asm("mov.b64 %0, {%1, %2};" : "=l"(r) : "r"(xu), "r"(yu));
    return r;
}
__device__ __forceinline__ uint64_t f2_dup(float x) {
    uint64_t r; uint32_t xu = __float_as_uint(x);
    asm("mov.b64 %0, {%1, %1};" : "=l"(r) : "r"(xu));
    return r;
}
__device__ __forceinline__ void f2_fma(uint64_t& d, uint64_t a, uint64_t b) {
    asm("fma.rn.f32x2 %0, %1, %2, %0;" : "+l"(d) : "l"(a), "l"(b));
}
__device__ __forceinline__ void f2_add(uint64_t& d, uint64_t a) {
    asm("add.rn.f32x2 %0, %1, %0;" : "+l"(d) : "l"(a));
}
__device__ __forceinline__ float2 f2_unpack(uint64_t v) {
    uint32_t lo, hi;
    asm("mov.b64 {%0, %1}, %2;" : "=r"(lo), "=r"(hi) : "l"(v));
    return make_float2(__uint_as_float(lo), __uint_as_float(hi));
}

// ---------------- dummy kernels: shift ncu -s 5 window onto lstm_rec ----------------
__global__ void dummy_kernel() {}

// ---------------- kernel 0: transpose h_prev -> g_hT[1] ----------------
__global__ void init_kernel(const float* __restrict__ h_prev) {
    int idx = blockIdx.x * blockDim.x + threadIdx.x;   // 0..32767
    int j = idx >> 6, b = idx & 63;
    g_hT[1][idx] = h_prev[(size_t)b * HID + j];
}

// ---------------- kernel 1: x_proj GEMM (FMA-bound f32x2, unchanged) ----------------
__global__ __launch_bounds__(256, 2) void xproj_gemm_kernel(
    const float* __restrict__ A,    // (131072, 512)
    const float* __restrict__ W,    // (2048, 512)
    const float* __restrict__ bi,
    const float* __restrict__ bh)
{
    __shared__ float Ash[16][132];
    __shared__ float Bsh[16][132];

    const int tid = threadIdx.x;
    const int tx = tid & 15;
    const int ty = tid >> 4;
    const int m0 = blockIdx.x * 128;
    const int g0 = blockIdx.y * 128;

    uint64_t acc[8][4];
#pragma unroll
    for (int g = 0; g < 8; ++g)
#pragma unroll
        for (int p = 0; p < 4; ++p) acc[g][p] = 0ull;

    for (int kt = 0; kt < 32; ++kt) {
        const int k0 = kt * 16;
#pragma unroll
        for (int i = 0; i < 2; ++i) {
            int idx = tid + i * 256;
            int r = idx >> 2, c4 = idx & 3;
            float4 va = *(const float4*)(A + (size_t)(m0 + r) * 512 + k0 + c4 * 4);
            Ash[c4 * 4 + 0][r] = va.x; Ash[c4 * 4 + 1][r] = va.y;
            Ash[c4 * 4 + 2][r] = va.z; Ash[c4 * 4 + 3][r] = va.w;
            float4 vb = *(const float4*)(W + (size_t)(g0 + r) * 512 + k0 + c4 * 4);
            Bsh[c4 * 4 + 0][r] = vb.x; Bsh[c4 * 4 + 1][r] = vb.y;
            Bsh[c4 * 4 + 2][r] = vb.z; Bsh[c4 * 4 + 3][r] = vb.w;
        }
        __syncthreads();
#pragma unroll
        for (int kk = 0; kk < 16; ++kk) {
            uint64_t a[4];
            const uint64_t* ap = (const uint64_t*)&Ash[kk][ty * 8];
            a[0] = ap[0]; a[1] = ap[1]; a[2] = ap[2]; a[3] = ap[3];
            float4 q0 = *(const float4*)&Bsh[kk][tx * 8];
            float4 q1 = *(const float4*)&Bsh[kk][tx * 8 + 4];
            float bv[8] = {q0.x, q0.y, q0.z, q0.w, q1.x, q1.y, q1.z, q1.w};
#pragma unroll
            for (int g = 0; g < 8; ++g) {
                uint64_t bd = f2_dup(bv[g]);
                f2_fma(acc[g][0], a[0], bd);
                f2_fma(acc[g][1], a[1], bd);
                f2_fma(acc[g][2], a[2], bd);
                f2_fma(acc[g][3], a[3], bd);
            }
        }
        __syncthreads();
    }

    const int s  = blockIdx.x * 2 + (ty >> 3);
    const int b0 = (ty & 7) * 8;
#pragma unroll
    for (int g = 0; g < 8; ++g) {
        int gg = g0 + tx * 8 + g;
        float bsum = __ldg(bi + gg) + __ldg(bh + gg);
        float2 p0 = f2_unpack(acc[g][0]);
        float2 p1 = f2_unpack(acc[g][1]);
        float2 p2 = f2_unpack(acc[g][2]);
        float2 p3 = f2_unpack(acc[g][3]);
        float4 v0 = make_float4(p0.x + bsum, p0.y + bsum, p1.x + bsum, p1.y + bsum);
        float4 v1 = make_float4(p2.x + bsum, p2.y + bsum, p3.x + bsum, p3.y + bsum);
        float* dst = g_xp + ((size_t)s * G4 + gg) * 64 + b0;
        *(float4*)dst = v0;
        *(float4*)(dst + 4) = v1;
    }
}

// ---------------- kernel 2: persistent recurrent LSTM ----------------
// R3 structure (128 blocks x 256 thr; block = 4 units x 64 batches; global barrier)
// + R4-lineage register-blocked inner loop (crossbar 2048 wf/step << 4096 FMA floor)
// + hierarchical barrier (8 leaves x16 -> root) + out stores off the fence path.
// Warp w owns k-slice [64w, 64w+64); lane=(rq in 2)x(bq in 16); tile = 4 row-pairs x 4 b.
__global__ __launch_bounds__(TPB, 1) void lstm_rec_kernel(
    const float* __restrict__ c_prev,
    const float* __restrict__ Whh,
    float* __restrict__ out)
{
    extern __shared__ char smp[];
    uint64_t* W2u  = (uint64_t*)smp;              // [512 k][8 rp] row-pairs, 32 KB
    char*     hreg = smp + 32768;                 // staging 128 KB (per-warp 16 KB); partials alias
    float*    zb   = (float*)(smp + 32768 + 131072);  // [16 rows][64 b], 4 KB
    float*    hbuf = (float*)(smp + 32768 + 131072 + 4096);  // [64 b][4 u], 1 KB

    const int tid  = threadIdx.x;
    const int w    = tid >> 5;       // 8 warps
    const int lane = tid & 31;
    const int rq   = lane >> 4;      // row-quad 0/1 (row-pairs rq*4 .. rq*4+3)
    const int bq   = lane & 15;      // b-quad 0..15
    const int u    = tid >> 6;       // activation: unit 0..3
    const int bb   = tid & 63;       // activation: batch
    const int ug   = blockIdx.x;
    const int j    = ug * 4 + u;

    // --- W setup: W2u[k*8+rp] = (Whh[row(2rp)][k], Whh[row(2rp+1)][k]);
    //     row r: gate = r>>2, unit = r&3 ---
    for (int idx = tid; idx < 512 * 8; idx += TPB) {
        int k = idx >> 3, rp = idx & 7;
        int r0 = 2 * rp, r1 = 2 * rp + 1;
        int row0 = (r0 >> 2) * HID + ug * 4 + (r0 & 3);
        int row1 = (r1 >> 2) * HID + ug * 4 + (r1 & 3);
        W2u[idx] = f2_pack(Whh[(size_t)row0 * HID + k], Whh[(size_t)row1 * HID + k]);
    }

    float c = c_prev[(size_t)bb * HID + j];
    float xi = g_xp[(size_t)(0 * HID + j) * 64 + bb];
    float xf = g_xp[(size_t)(1 * HID + j) * 64 + bb];
    float xg = g_xp[(size_t)(2 * HID + j) * 64 + bb];
    float xo = g_xp[(size_t)(3 * HID + j) * 64 + bb];

    float* hst = (float*)(hreg + w * 16384);      // warp slice [64 k local][64 b]
    uint32_t hst_s = (uint32_t)__cvta_generic_to_shared(hst);
    const uint64_t* W2w = W2u + (size_t)w * 64 * 8;   // warp's global-k W base

    __syncthreads();   // W2u ready

    for (int s = 0; s < SLEN; ++s) {
        // --- stage warp's 16KB h slice: 4 chunks of 16 k, all issued upfront ---
        const float* hsrc = g_hT[(s + 1) & 1] + (size_t)w * 64 * 64;
#pragma unroll
        for (int ch = 0; ch < 4; ++ch) {
#pragma unroll
            for (int i = 0; i < 8; ++i) {
                int flat = ch * 256 + i * 32 + lane;   // float4 index
                asm volatile("cp.async.cg.shared.global [%0], [%1], 16;"
                             :: "r"(hst_s + flat * 16), "l"(hsrc + flat * 4));
            }
            asm volatile("cp.async.commit_group;");
        }

        uint64_t acc[4][4];    // [row-pair local][b local]
#pragma unroll
        for (int i = 0; i < 4; ++i)
#pragma unroll
            for (int p = 0; p < 4; ++p) acc[i][p] = 0ull;

        const float zxi = xi, zxf = xf, zxg = xg, zxo = xo;
        if (s + 1 < SLEN) {    // prefetch next xp under compute
            size_t nb = (size_t)(s + 1) * G4 * 64;
            xi = g_xp[nb + (size_t)(0 * HID + j) * 64 + bb];
            xf = g_xp[nb + (size_t)(1 * HID + j) * 64 + bb];
            xg = g_xp[nb + (size_t)(2 * HID + j) * 64 + bb];
            xo = g_xp[nb + (size_t)(3 * HID + j) * 64 + bb];
        }

#pragma unroll
        for (int ch = 0; ch < 4; ++ch) {
            switch (ch) {
                case 0: asm volatile("cp.async.wait_group 3;"); break;
                case 1: asm volatile("cp.async.wait_group 2;"); break;
                case 2: asm volatile("cp.async.wait_group 1;"); break;
                default: asm volatile("cp.async.wait_group 0;");
            }
            __syncwarp();
#pragma unroll
            for (int kk = 0; kk < 16; ++kk) {
                const int k = ch * 16 + kk;            // local k
                float4 hq = *(const float4*)(hst + k * 64 + bq * 4);
                uint64_t h0 = f2_dup(hq.x), h1 = f2_dup(hq.y);
                uint64_t h2 = f2_dup(hq.z), h3 = f2_dup(hq.w);
                const uint64_t* Wk = W2w + (size_t)k * 8 + rq * 4;
                ulonglong2 wA = *(const ulonglong2*)Wk;        // rp 0,1 (local)
                ulonglong2 wB = *(const ulonglong2*)(Wk + 2);  // rp 2,3
                f2_fma(acc[0][0], h0, wA.x); f2_fma(acc[0][1], h1, wA.x);
                f2_fma(acc[0][2], h2, wA.x); f2_fma(acc[0][3], h3, wA.x);
                f2_fma(acc[1][0], h0, wA.y); f2_fma(acc[1][1], h1, wA.y);
                f2_fma(acc[1][2], h2, wA.y); f2_fma(acc[1][3], h3, wA.y);
                f2_fma(acc[2][0], h0, wB.x); f2_fma(acc[2][1], h1, wB.x);
                f2_fma(acc[2][2], h2, wB.x); f2_fma(acc[2][3], h3, wB.x);
                f2_fma(acc[3][0], h0, wB.y); f2_fma(acc[3][1], h1, wB.y);
                f2_fma(acc[3][2], h2, wB.y); f2_fma(acc[3][3], h3, wB.y);
            }
        }

        // --- partials into per-warp region (aliases staging, all consumed) ---
        __syncthreads();
        {
            uint64_t* part = (uint64_t*)hreg + (size_t)w * 512;   // [8 rp][64 b] pairs
#pragma unroll
            for (int rpl = 0; rpl < 4; ++rpl) {
#pragma unroll
                for (int bi = 0; bi < 4; bi += 2) {
                    int p = (rq * 4 + rpl) * 64 + bq * 4 + bi;
                    *(ulonglong2*)(part + p) =
                        make_ulonglong2(acc[rpl][bi], acc[rpl][bi + 1]);
                }
            }
        }
        __syncthreads();

        // --- reduce over 8 warps: thread t owns pairs 2t, 2t+1 ---
        {
            const uint64_t* part = (const uint64_t*)hreg;
            ulonglong2 v0 = *(const ulonglong2*)(part + 2 * tid);
            uint64_t e = v0.x, o = v0.y;
#pragma unroll
            for (int ww = 1; ww < 8; ++ww) {
                ulonglong2 v = *(const ulonglong2*)(part + ww * 512 + 2 * tid);
                f2_add(e, v.x);
                f2_add(o, v.y);
            }
            // pair p = rp*64 + b; p0 = 2t (b even), p1 = 2t+1
            int rp = tid >> 5;            // (2t)>>6
            int b  = (2 * tid) & 63;
            float2 E = f2_unpack(e), O = f2_unpack(o);
            *(float2*)&zb[(2 * rp) * 64 + b]     = make_float2(E.x, O.x);
            *(float2*)&zb[(2 * rp + 1) * 64 + b] = make_float2(E.y, O.y);
        }
        __syncthreads();

        // --- activations: thread (u, bb) ---
        {
            float z_i = zb[(0 * 4 + u) * 64 + bb] + zxi;
            float z_f = zb[(1 * 4 + u) * 64 + bb] + zxf;
            float z_g = zb[(2 * 4 + u) * 64 + bb] + zxg;
            float z_o = zb[(3 * 4 + u) * 64 + bb] + zxo;
            float ig = 1.f / (1.f + __expf(-z_i));
            float fg = 1.f / (1.f + __expf(-z_f));
            float gt = tanhf(z_g);
            float og = 1.f / (1.f + __expf(-z_o));
            c = fg * c + ig * gt;
            float h = og * tanhf(c);

            g_hT[s & 1][j * 64 + bb] = h;     // coalesced (bb consecutive)
            hbuf[bb * 4 + u] = h;

            if (s == SLEN - 1) {
                const size_t SBH = (size_t)SLEN * BATCH * HID;
                size_t o2 = (size_t)bb * HID + j;
                out[SBH + o2] = h;                          // h_f
                out[SBH + (size_t)BATCH * HID + o2] = c;    // c_f
            }
        }
        __syncthreads();

        // --- hierarchical barrier arrive (tid0), out stores hidden under spin ---
        unsigned e0;
        if (tid == 0) {
            asm volatile("ld.relaxed.gpu.global.u32 %0, [%1];"
                         : "=r"(e0) : "l"(&g_epoch) : "memory");
            asm volatile("membar.gl;" ::: "memory");
            unsigned old;
            asm volatile("atom.add.acq_rel.gpu.global.u32 %0, [%1], %2;"
                         : "=r"(old) : "l"(&g_leaf[ug >> 4]), "r"(1u) : "memory");
            if (old == 15u) {
                asm volatile("st.relaxed.gpu.global.u32 [%0], %1;"
                             :: "l"(&g_leaf[ug >> 4]), "r"(0u) : "memory");
                unsigned rold;
                asm volatile("atom.add.acq_rel.gpu.global.u32 %0, [%1], %2;"
                             : "=r"(rold) : "l"(&g_root), "r"(1u) : "memory");
                if (rold == 7u) {
                    asm volatile("st.relaxed.gpu.global.u32 [%0], %1;"
                                 :: "l"(&g_root), "r"(0u) : "memory");
                    asm volatile("red.add.release.gpu.global.u32 [%0], %1;"
                                 :: "l"(&g_epoch), "r"(1u) : "memory");
                }
            }
        }

        // out stores: coalesced float4, off the barrier-release path
        if (tid < 64) {
            float4 hv = *(const float4*)(hbuf + tid * 4);
            *(float4*)(out + ((size_t)s * BATCH + tid) * HID + ug * 4) = hv;
        }

        if (tid == 0) {
            unsigned cur;
            do {
                __nanosleep(32);
                asm volatile("ld.acquire.gpu.global.u32 %0, [%1];"
                             : "=r"(cur) : "l"(&g_epoch) : "memory");
            } while (cur == e0);
        }
        __syncthreads();
    }
}

// ---------------- launch ----------------
extern "C" void kernel_launch(void* const* d_in, const int* in_sizes, int n_in,
                              void* d_out, int out_size) {
    (void)in_sizes; (void)n_in; (void)out_size;
    const float* input  = (const float*)d_in[0];  // (2048, 64, 512)
    const float* h_prev = (const float*)d_in[1];  // (64, 512)
    const float* c_prev = (const float*)d_in[2];  // (64, 512)
    const float* w_ih   = (const float*)d_in[3];  // (2048, 512)
    const float* w_hh   = (const float*)d_in[4];  // (2048, 512)
    const float* b_ih   = (const float*)d_in[5];  // (2048,)
    const float* b_hh   = (const float*)d_in[6];  // (2048,)
    float* out = (float*)d_out;

    cudaFuncSetAttribute(lstm_rec_kernel,
                         cudaFuncAttributeMaxDynamicSharedMemorySize, 172032);

    // 3 dummies: per-replay launch sequence = d,d,d,init,gemm,rec
    // so ncu (-s 5 -c 1) profiles lstm_rec_kernel.
    dummy_kernel<<<1, 32>>>();
    dummy_kernel<<<1, 32>>>();
    dummy_kernel<<<1, 32>>>();

    init_kernel<<<128, 256>>>(h_prev);

    dim3 g1(131072 / 128, 2048 / 128);   // (1024, 16)
    xproj_gemm_kernel<<<g1, 256>>>(input, w_ih, b_ih, b_hh);

    lstm_rec_kernel<<<NBLK, TPB, 172032>>>(c_prev, w_hh, out);
}